// round 3
// baseline (speedup 1.0000x reference)
#include <cuda_runtime.h>
#include <cuda_bf16.h>
#include <math.h>

// Problem shape (fixed by reference setup_inputs)
#define NN   32
#define CC   256
#define HH   56
#define WW   56
#define HWp  (HH * WW)        // 3136
#define NHWc (NN * HWp)       // 100352
#define KK   3
#define NW   (CC * CC * KK * KK)  // 589824

// ---------------------------------------------------------------------------
// Scratch (device globals only — no allocation allowed)
// ---------------------------------------------------------------------------
__device__ int       g_s[NHWc];          // per-pixel channel-sum of sign(x)
__device__ int       g_base[NHWc];       // 3x3 boxsum of g_s  (== y for wb==+1 everywhere)
__device__ long long g_base_sum;
__device__ long long g_base_sumsq;
__device__ int       g_corr_cnt[CC];            // # of non-(+1) weight entries per out-channel
__device__ int       g_corr_ent[CC * CC * 9];   // packed (ci<<8 | kh<<4 | kw<<2 | cmag), cmag in {1,2}
__device__ float     g_scale[CC];
__device__ float     g_shift[CC];

// ---------------------------------------------------------------------------
// K0: reset accumulators (kernel_launch must be deterministic across replays)
// ---------------------------------------------------------------------------
__global__ void k_init() {
    int t = threadIdx.x;
    if (t < CC) g_corr_cnt[t] = 0;
    if (t == 0) { g_base_sum = 0; g_base_sumsq = 0; }
}

// ---------------------------------------------------------------------------
// K1: scan weights, record every entry whose sign(w) != +1.
//     wb = sign(w);  coefficient in correction conv = (wb - 1) = -cmag
//       w > 0  -> wb=+1 -> skip
//       w == 0 -> wb= 0 -> cmag=1
//       w < 0  -> wb=-1 -> cmag=2
// ---------------------------------------------------------------------------
__global__ void k_wscan(const float* __restrict__ w) {
    int idx = blockIdx.x * blockDim.x + threadIdx.x;
    if (idx >= NW) return;
    float wv = w[idx];
    if (wv > 0.f) return;
    int co = idx / (CC * 9);
    int r  = idx - co * (CC * 9);
    int ci = r / 9;
    int t  = r - ci * 9;
    int kh = t / 3, kw = t - kh * 3;
    int cmag = (wv < 0.f) ? 2 : 1;
    int pos = atomicAdd(&g_corr_cnt[co], 1);
    g_corr_ent[co * (CC * 9) + pos] = (ci << 8) | (kh << 4) | (kw << 2) | cmag;
}

// ---------------------------------------------------------------------------
// K2: s[n,h,w] = sum_ci sign(x[n,ci,h,w])   (reads all of x once, coalesced)
// ---------------------------------------------------------------------------
__global__ void k_colsum(const float* __restrict__ x) {
    int idx = blockIdx.x * blockDim.x + threadIdx.x;   // over NHWc
    int n  = idx / HWp;
    int hw = idx - n * HWp;
    const float* p = x + (size_t)n * CC * HWp + hw;
    int acc = 0;
    #pragma unroll 8
    for (int ci = 0; ci < CC; ci++) {
        float v = p[(size_t)ci * HWp];
        acc += (v > 0.f) - (v < 0.f);
    }
    g_s[idx] = acc;
}

// ---------------------------------------------------------------------------
// K3: base = 3x3 zero-padded boxsum of s; also reduce exact sum / sumsq
// ---------------------------------------------------------------------------
__global__ void k_base() {
    int idx = blockIdx.x * blockDim.x + threadIdx.x;   // over NHWc
    int n  = idx / HWp;
    int hw = idx - n * HWp;
    int h  = hw / WW, w0 = hw - h * WW;
    const int* sp = g_s + n * HWp;
    int acc = 0;
    #pragma unroll
    for (int kh = 0; kh < 3; kh++) {
        int hh = h + kh - 1;
        if ((unsigned)hh >= HH) continue;
        #pragma unroll
        for (int kw = 0; kw < 3; kw++) {
            int ww = w0 + kw - 1;
            if ((unsigned)ww < WW) acc += sp[hh * WW + ww];
        }
    }
    g_base[idx] = acc;

    long long s1 = acc;
    long long s2 = (long long)acc * (long long)acc;
    #pragma unroll
    for (int o = 16; o; o >>= 1) {
        s1 += __shfl_down_sync(0xffffffffu, s1, o);
        s2 += __shfl_down_sync(0xffffffffu, s2, o);
    }
    __shared__ long long sh1[8], sh2[8];
    int lane = threadIdx.x & 31, wid = threadIdx.x >> 5;
    if (lane == 0) { sh1[wid] = s1; sh2[wid] = s2; }
    __syncthreads();
    if (threadIdx.x == 0) {
        long long t1 = 0, t2 = 0;
        #pragma unroll
        for (int i = 0; i < 8; i++) { t1 += sh1[i]; t2 += sh2[i]; }
        atomicAdd((unsigned long long*)&g_base_sum,   (unsigned long long)t1);
        atomicAdd((unsigned long long*)&g_base_sumsq, (unsigned long long)t2);
    }
}

// ---------------------------------------------------------------------------
// K4: per-channel BN stats -> scale/shift.
//     Channels with no weight corrections share the base statistics (O(1)).
//     Corrected channels recompute y = base + sum_j (wb_j-1)*sign(x[...]) exactly.
// ---------------------------------------------------------------------------
__global__ void k_stats(const float* __restrict__ x,
                        const float* __restrict__ gamma,
                        const float* __restrict__ beta) {
    int c = blockIdx.x;
    int cnt = g_corr_cnt[c];

    if (cnt == 0) {
        if (threadIdx.x == 0) {
            double mean = (double)g_base_sum   / (double)NHWc;
            double var  = (double)g_base_sumsq / (double)NHWc - mean * mean;
            double rstd = 1.0 / sqrt(var + 1e-5);
            float sc = gamma[c] * (float)rstd;
            g_scale[c] = sc;
            g_shift[c] = beta[c] - sc * (float)mean;
        }
        return;
    }

    const int* ents = g_corr_ent + c * (CC * 9);
    long long s1 = 0, s2 = 0;
    for (int e = threadIdx.x; e < NHWc; e += blockDim.x) {
        int n  = e / HWp;
        int hw = e - n * HWp;
        int h  = hw / WW, w0 = hw - h * WW;
        int y = g_base[e];
        for (int j = 0; j < cnt; j++) {
            int ent = ents[j];
            int ci = ent >> 8, kh = (ent >> 4) & 3, kw = (ent >> 2) & 3, cm = ent & 3;
            int hh = h + kh - 1, ww = w0 + kw - 1;
            if ((unsigned)hh < HH && (unsigned)ww < WW) {
                float xv = x[((size_t)n * CC + ci) * HWp + hh * WW + ww];
                int sg = (xv > 0.f) - (xv < 0.f);
                y -= cm * sg;
            }
        }
        s1 += y;
        s2 += (long long)y * (long long)y;
    }
    #pragma unroll
    for (int o = 16; o; o >>= 1) {
        s1 += __shfl_down_sync(0xffffffffu, s1, o);
        s2 += __shfl_down_sync(0xffffffffu, s2, o);
    }
    __shared__ long long sh1[8], sh2[8];
    int lane = threadIdx.x & 31, wid = threadIdx.x >> 5;
    if (lane == 0) { sh1[wid] = s1; sh2[wid] = s2; }
    __syncthreads();
    if (threadIdx.x == 0) {
        long long t1 = 0, t2 = 0;
        #pragma unroll
        for (int i = 0; i < 8; i++) { t1 += sh1[i]; t2 += sh2[i]; }
        double mean = (double)t1 / (double)NHWc;
        double var  = (double)t2 / (double)NHWc - mean * mean;
        double rstd = 1.0 / sqrt(var + 1e-5);
        float sc = gamma[c] * (float)rstd;
        g_scale[c] = sc;
        g_shift[c] = beta[c] - sc * (float)mean;
    }
}

// ---------------------------------------------------------------------------
// K5: out = scale[c]*y + shift[c] + x   (float4 vectorized; one block per
//     (n,c) plane, 784 threads * 4 pixels = 3136)
// ---------------------------------------------------------------------------
__global__ void k_final(const float* __restrict__ x, float* __restrict__ out) {
    int b = blockIdx.x;
    int n = b >> 8, c = b & 255;
    float sc = g_scale[c], sh = g_shift[c];
    int cnt = g_corr_cnt[c];
    int p = threadIdx.x * 4;                 // 4 pixels, same row (56 % 4 == 0)
    size_t plane = ((size_t)n * CC + c) * HWp;

    float4 xv = *(const float4*)(x + plane + p);
    int4 bi   = *(const int4*)(g_base + n * HWp + p);
    int y0 = bi.x, y1 = bi.y, y2 = bi.z, y3 = bi.w;

    if (cnt) {
        int h = p / WW, w0 = p - h * WW;
        const int* ents = g_corr_ent + c * (CC * 9);
        for (int j = 0; j < cnt; j++) {
            int ent = ents[j];
            int ci = ent >> 8, kh = (ent >> 4) & 3, kw = (ent >> 2) & 3, cm = ent & 3;
            int hh = h + kh - 1;
            if ((unsigned)hh >= HH) continue;
            const float* xr = x + ((size_t)n * CC + ci) * HWp + hh * WW;
            #pragma unroll
            for (int jj = 0; jj < 4; jj++) {
                int ww = w0 + jj + kw - 1;
                if ((unsigned)ww < WW) {
                    float v = xr[ww];
                    int d = cm * ((v > 0.f) - (v < 0.f));
                    if      (jj == 0) y0 -= d;
                    else if (jj == 1) y1 -= d;
                    else if (jj == 2) y2 -= d;
                    else              y3 -= d;
                }
            }
        }
    }

    float4 o;
    o.x = fmaf(sc, (float)y0, sh) + xv.x;
    o.y = fmaf(sc, (float)y1, sh) + xv.y;
    o.z = fmaf(sc, (float)y2, sh) + xv.z;
    o.w = fmaf(sc, (float)y3, sh) + xv.w;
    *(float4*)(out + plane + p) = o;
}

// ---------------------------------------------------------------------------
// kernel_launch — inputs: x, w, gamma, beta ; output: float32 [32,256,56,56]
// ---------------------------------------------------------------------------
extern "C" void kernel_launch(void* const* d_in, const int* in_sizes, int n_in,
                              void* d_out, int out_size) {
    const float* x     = (const float*)d_in[0];
    const float* w     = (const float*)d_in[1];
    const float* gamma = (const float*)d_in[2];
    const float* beta  = (const float*)d_in[3];
    float* out = (float*)d_out;

    k_init  <<<1, 256>>>();
    k_wscan <<<(NW + 255) / 256, 256>>>(w);
    k_colsum<<<NHWc / 256, 256>>>(x);
    k_base  <<<NHWc / 256, 256>>>();
    k_stats <<<CC, 256>>>(x, gamma, beta);
    k_final <<<NN * CC, HWp / 4>>>(x, out);
}